// round 14
// baseline (speedup 1.0000x reference)
#include <cuda_runtime.h>
#include <cstdint>
#include <cstddef>

#define T_STEPS 2048
#define B_SIZE  256
#define I_SIZE  64
#define H_SIZE  128

// Scratch: input projections x@Wi + bi, layout [T][B][3*H] (805 MB)
__device__ float g_xproj[(size_t)T_STEPS * B_SIZE * 3 * H_SIZE];
// Scratch: hidden states hs [T][B][H] (268 MB) for deferred classifier
__device__ float g_hs[(size_t)T_STEPS * B_SIZE * H_SIZE];

__device__ __forceinline__ float sigmoidf_(float x) {
    return 1.0f / (1.0f + __expf(-x));
}
__device__ __forceinline__ float tanhf_(float x) {
    return 1.0f - 2.0f / (1.0f + __expf(2.0f * x));
}

// ---- packed f32x2 helpers (Blackwell FFMA2 / FADD2) ------------------------
__device__ __forceinline__ unsigned long long fma2_(unsigned long long a,
                                                    unsigned long long b,
                                                    unsigned long long c) {
    unsigned long long d;
    asm("fma.rn.f32x2 %0, %1, %2, %3;" : "=l"(d) : "l"(a), "l"(b), "l"(c));
    return d;
}
__device__ __forceinline__ unsigned long long add2_(unsigned long long a,
                                                    unsigned long long b) {
    unsigned long long d;
    asm("add.rn.f32x2 %0, %1, %2;" : "=l"(d) : "l"(a), "l"(b));
    return d;
}
__device__ __forceinline__ unsigned long long dup2_(float x) {
    unsigned long long d;
    asm("mov.b64 %0, {%1, %1};" : "=l"(d) : "f"(x));
    return d;
}
__device__ __forceinline__ unsigned long long pack2_(float a, float b) {
    unsigned long long d;
    asm("mov.b64 %0, {%1, %2};" : "=l"(d) : "f"(a), "f"(b));
    return d;
}
__device__ __forceinline__ float2 unpack2_(unsigned long long v) {
    float2 r;
    asm("mov.b64 {%0, %1}, %2;" : "=f"(r.x), "=f"(r.y) : "l"(v));
    return r;
}

// ============================================================================
// Phase 1: xproj — EXACT R10 kernel (best measured: 615-618 us).
// Block tile = 64 rows x 128 cols (one gate), 128 threads, 4x16 register tile
// packed f32x2 over cols, XOR-swizzled transposed x tile. SMEM 48KB.
// ============================================================================
#define XS_IDX(i, row) ((i) * 64 + ((row) ^ ((i) & 60)))

__global__ __launch_bounds__(128, 3) void xproj_kernel(
    const float* __restrict__ x,
    const float* __restrict__ Wir, const float* __restrict__ Wiz, const float* __restrict__ Win,
    const float* __restrict__ bir, const float* __restrict__ biz, const float* __restrict__ bin_)
{
    __shared__ __align__(16) float xs[I_SIZE * 64];       // 16384 B
    __shared__ __align__(16) float ws[I_SIZE * H_SIZE];   // 32768 B

    const int g = blockIdx.y;
    const float* __restrict__ W    = (g == 0) ? Wir : (g == 1) ? Wiz : Win;
    const float* __restrict__ bias = (g == 0) ? bir : (g == 1) ? biz : bin_;

    const int tid = threadIdx.x;
    const size_t r_base = (size_t)blockIdx.x * 64;

    const float4* __restrict__ xg4 = (const float4*)(x + r_base * I_SIZE);
    #pragma unroll
    for (int s = 0; s < 8; s++) {
        int idx4 = tid + 128 * s;            // 0..1023 float4s
        float4 v = xg4[idx4];
        int row = idx4 >> 4;
        int i0  = (idx4 & 15) * 4;
        xs[XS_IDX(i0 + 0, row)] = v.x;
        xs[XS_IDX(i0 + 1, row)] = v.y;
        xs[XS_IDX(i0 + 2, row)] = v.z;
        xs[XS_IDX(i0 + 3, row)] = v.w;
    }
    const float4* __restrict__ Wg4 = (const float4*)W;
    #pragma unroll
    for (int s = 0; s < 16; s++) {
        int idx4 = tid + 128 * s;
        ((float4*)ws)[idx4] = Wg4[idx4];
    }
    __syncthreads();

    const int tr = tid & 15;
    const int tc = tid >> 4;
    const int r0 = tr * 4;
    const int c0 = tc * 16;

    unsigned long long accp[4][8];
    #pragma unroll
    for (int r = 0; r < 4; r++)
        #pragma unroll
        for (int c = 0; c < 8; c++)
            accp[r][c] = 0ull;

    #pragma unroll 4
    for (int k = 0; k < I_SIZE; k++) {
        float4 xa = *(const float4*)&xs[XS_IDX(k, r0)];
        const ulonglong2* wr = (const ulonglong2*)&ws[k * H_SIZE + c0];
        ulonglong2 wq0 = wr[0], wq1 = wr[1], wq2 = wr[2], wq3 = wr[3];
        unsigned long long wp[8] = {wq0.x, wq0.y, wq1.x, wq1.y,
                                    wq2.x, wq2.y, wq3.x, wq3.y};
        unsigned long long xd[4] = {dup2_(xa.x), dup2_(xa.y), dup2_(xa.z), dup2_(xa.w)};
        #pragma unroll
        for (int r = 0; r < 4; r++)
            #pragma unroll
            for (int c = 0; c < 8; c++)
                accp[r][c] = fma2_(xd[r], wp[c], accp[r][c]);
    }

    const float4* __restrict__ bp = (const float4*)(bias + c0);
    float4 b0 = bp[0], b1 = bp[1], b2 = bp[2], b3 = bp[3];
    float bv[16] = {b0.x, b0.y, b0.z, b0.w, b1.x, b1.y, b1.z, b1.w,
                    b2.x, b2.y, b2.z, b2.w, b3.x, b3.y, b3.z, b3.w};

    #pragma unroll
    for (int r = 0; r < 4; r++) {
        size_t row = r_base + (size_t)(r0 + r);
        float* op = g_xproj + row * (3 * H_SIZE) + g * H_SIZE + c0;
        #pragma unroll
        for (int q = 0; q < 4; q++) {
            float2 pa = unpack2_(accp[r][2 * q + 0]);
            float2 pb = unpack2_(accp[r][2 * q + 1]);
            float4 o;
            o.x = pa.x + bv[4 * q + 0];
            o.y = pa.y + bv[4 * q + 1];
            o.z = pb.x + bv[4 * q + 2];
            o.w = pb.y + bv[4 * q + 3];
            *(float4*)(op + 4 * q) = o;
        }
    }
}

// packed dot over one h row (128 floats as 32 ulonglong2, broadcast LDS.128)
#define ROW_DOT(hq, ACC)                                          \
    do {                                                          \
        unsigned long long q0 = 0ull, q1 = 0ull, q2 = 0ull, q3 = 0ull; \
        _Pragma("unroll")                                         \
        for (int m = 0; m < 16; m++) {                            \
            ulonglong2 va = (hq)[2 * m];                          \
            ulonglong2 vb = (hq)[2 * m + 1];                      \
            q0 = fma2_(va.x, w2[4 * m + 0], q0);                  \
            q1 = fma2_(va.y, w2[4 * m + 1], q1);                  \
            q2 = fma2_(vb.x, w2[4 * m + 2], q2);                  \
            q3 = fma2_(vb.y, w2[4 * m + 3], q3);                  \
        }                                                         \
        unsigned long long qs = add2_(add2_(q0, q1), add2_(q2, q3)); \
        float2 uu = unpack2_(qs);                                 \
        (ACC) = uu.x + uu.y;                                      \
    } while (0)

// ============================================================================
// Phase 2: persistent per-batch GRU recurrence — row-skewed 2-stage pipeline.
// grid = 128 blocks (2 batch rows each), 384 threads, thread = (gate g, col j).
// Each step = 2 intervals (2 barriers, same as before), but each epilogue is
// overlapped with the OTHER row's dot, hiding the epilogue tail:
//   interval A: dot(row0, t)  || epi(row1, t-1)   [epi by g1]
//   interval B: dot(row1, t)  || epi(row0, t)     [epi by g2]
// Cross-barrier register carry: g2 keeps (acc0+bhn, x0n); g1 keeps z1.
// ============================================================================
__global__ __launch_bounds__(384, 1) void gru_kernel(
    const float* __restrict__ Whr, const float* __restrict__ Whz, const float* __restrict__ Whn,
    const float* __restrict__ bhn)
{
    __shared__ __align__(16) float h_s[2][H_SIZE];
    __shared__ float r_s[2][H_SIZE];
    __shared__ float z0_s[H_SIZE];                 // z row 0 (A -> B)
    __shared__ __align__(8) float2 ax1_s[H_SIZE];  // (acc1 + bhn, x1n) (B -> next A)

    const int tid = threadIdx.x;
    const int g   = tid >> 7;       // 0=r, 1=z, 2=n
    const int j   = tid & 127;
    const int b0  = blockIdx.x * 2;

    const float* __restrict__ Wh = (g == 0) ? Whr : (g == 1) ? Whz : Whn;

    // Register-resident weight column packed over k pairs (128 regs).
    unsigned long long w2[H_SIZE / 2];
    #pragma unroll
    for (int m = 0; m < H_SIZE / 2; m++)
        w2[m] = pack2_(Wh[(2 * m) * H_SIZE + j], Wh[(2 * m + 1) * H_SIZE + j]);

    const float bhn_j = bhn[j];

    if (tid < 2 * H_SIZE) ((float*)h_s)[tid] = 0.0f;   // h(-1) = 0 both rows
    __syncthreads();

    const float* __restrict__ xp = g_xproj + (size_t)b0 * (3 * H_SIZE) + g * H_SIZE + j;
    const size_t step_stride = (size_t)B_SIZE * 3 * H_SIZE;

    const ulonglong2* __restrict__ h0q = (const ulonglong2*)h_s[0];
    const ulonglong2* __restrict__ h1q = (const ulonglong2*)h_s[1];

    float x0 = xp[0];
    float x1 = xp[3 * H_SIZE];

    float a0n_r = 0.0f, x0n_r = 0.0f;   // g2: row0 n-dot carry (A -> B)
    float z1_r  = 0.0f;                 // g1: row1 z carry (B -> next A)

    for (int t = 0; t < T_STEPS; t++) {
        // branchless prefetch of x(t+1)
        int tn = (t + 1 < T_STEPS) ? (t + 1) : t;
        const float* xq = xp + (size_t)tn * step_stride;
        float nx0 = xq[0];
        float nx1 = xq[3 * H_SIZE];

        // ---------------- interval A: dot(row0, t) || epi(row1, t-1) --------
        float acc0;
        ROW_DOT(h0q, acc0);

        if (g == 0) {
            r_s[0][j] = sigmoidf_(x0 + acc0);
        } else if (g == 1) {
            z0_s[j] = sigmoidf_(x0 + acc0);
            if (t > 0) {
                // epilogue row1 for step t-1
                float h1o = h_s[1][j];               // h1(t-2)
                float2 ax = ax1_s[j];                // (acc1+bhn, x1n) from B(t-1)
                float n1  = tanhf_(fmaf(r_s[1][j], ax.x, ax.y));
                float hn1 = fmaf(z1_r, h1o - n1, n1);
                h_s[1][j] = hn1;                     // h1(t-1)
                g_hs[((size_t)(t - 1) * B_SIZE + b0 + 1) * H_SIZE + j] = hn1;
            }
        } else {
            a0n_r = acc0 + bhn_j;                    // carry in regs
            x0n_r = x0;
        }
        __syncthreads();

        // ---------------- interval B: dot(row1, t) || epi(row0, t) ----------
        float acc1;
        ROW_DOT(h1q, acc1);

        if (g == 0) {
            r_s[1][j] = sigmoidf_(x1 + acc1);
        } else if (g == 1) {
            z1_r = sigmoidf_(x1 + acc1);             // carry in reg
        } else {
            float2 ax;
            ax.x = acc1 + bhn_j;
            ax.y = x1;
            ax1_s[j] = ax;
            // epilogue row0 for step t (acc carried in regs across barrier)
            float h0o = h_s[0][j];                   // h0(t-1)
            float n0  = tanhf_(fmaf(r_s[0][j], a0n_r, x0n_r));
            float z0  = z0_s[j];
            float hn0 = fmaf(z0, h0o - n0, n0);
            h_s[0][j] = hn0;                         // h0(t)
            g_hs[((size_t)t * B_SIZE + b0) * H_SIZE + j] = hn0;
        }
        __syncthreads();

        x0 = nx0;
        x1 = nx1;
    }

    // pipeline tail: epilogue row1 for t = T-1 (uses B(T-1) outputs)
    if (g == 1) {
        float h1o = h_s[1][j];                       // h1(T-2)
        float2 ax = ax1_s[j];
        float n1  = tanhf_(fmaf(r_s[1][j], ax.x, ax.y));
        float hn1 = fmaf(z1_r, h1o - n1, n1);
        g_hs[((size_t)(T_STEPS - 1) * B_SIZE + b0 + 1) * H_SIZE + j] = hn1;
    }
}

// ============================================================================
// Phase 3: classifier out[o] = sigmoid(dot(hs[o,:], Wc) + bc).
// Warp per output; memory-bound (268 MB streamed).
// ============================================================================
__global__ __launch_bounds__(256) void cls_kernel(
    const float* __restrict__ Wc, const float* __restrict__ bc,
    float* __restrict__ out)
{
    const int lane = threadIdx.x & 31;
    const size_t o = (size_t)blockIdx.x * 8 + (threadIdx.x >> 5);

    float4 h4 = *(const float4*)&g_hs[o * H_SIZE + lane * 4];
    float4 w4 = *(const float4*)&Wc[lane * 4];
    float v = fmaf(h4.x, w4.x, fmaf(h4.y, w4.y, fmaf(h4.z, w4.z, h4.w * w4.w)));
    #pragma unroll
    for (int off = 16; off > 0; off >>= 1)
        v += __shfl_down_sync(0xffffffffu, v, off);
    if (lane == 0) out[o] = sigmoidf_(v + bc[0]);
}

// ============================================================================
extern "C" void kernel_launch(void* const* d_in, const int* in_sizes, int n_in,
                              void* d_out, int out_size)
{
    const float* x    = (const float*)d_in[0];
    const float* Wir  = (const float*)d_in[1];
    const float* Wiz  = (const float*)d_in[2];
    const float* Win  = (const float*)d_in[3];
    const float* bir  = (const float*)d_in[4];
    const float* biz  = (const float*)d_in[5];
    const float* bin_ = (const float*)d_in[6];
    const float* Whr  = (const float*)d_in[7];
    const float* Whz  = (const float*)d_in[8];
    const float* Whn  = (const float*)d_in[9];
    const float* bhn  = (const float*)d_in[10];
    const float* Wc   = (const float*)d_in[11];
    const float* bc   = (const float*)d_in[12];
    float* out = (float*)d_out;

    // Phase 1: input projections (exact R10 kernel).
    dim3 grid1((T_STEPS * B_SIZE) / 64, 3);
    xproj_kernel<<<grid1, 128>>>(x, Wir, Wiz, Win, bir, biz, bin_);

    // Phase 2: row-skewed sequential recurrence, 128 blocks.
    gru_kernel<<<B_SIZE / 2, 384>>>(Whr, Whz, Whn, bhn);

    // Phase 3: classifier over all T*B hidden states.
    cls_kernel<<<(T_STEPS * B_SIZE) / 8, 256>>>(Wc, bc, out);
}

// round 15
// speedup vs baseline: 1.0714x; 1.0714x over previous
#include <cuda_runtime.h>
#include <cstdint>
#include <cstddef>

#define T_STEPS 2048
#define B_SIZE  256
#define I_SIZE  64
#define H_SIZE  128

// Scratch: input projections x@Wi + bi, layout [T][B][3*H] (805 MB)
__device__ float g_xproj[(size_t)T_STEPS * B_SIZE * 3 * H_SIZE];
// Scratch: hidden states hs [T][B][H] (268 MB) for deferred classifier
__device__ float g_hs[(size_t)T_STEPS * B_SIZE * H_SIZE];

__device__ __forceinline__ float sigmoidf_(float x) {
    return 1.0f / (1.0f + __expf(-x));
}
__device__ __forceinline__ float tanhf_(float x) {
    return 1.0f - 2.0f / (1.0f + __expf(2.0f * x));
}

// ---- packed f32x2 helpers (Blackwell FFMA2 / FADD2) ------------------------
__device__ __forceinline__ unsigned long long fma2_(unsigned long long a,
                                                    unsigned long long b,
                                                    unsigned long long c) {
    unsigned long long d;
    asm("fma.rn.f32x2 %0, %1, %2, %3;" : "=l"(d) : "l"(a), "l"(b), "l"(c));
    return d;
}
__device__ __forceinline__ unsigned long long add2_(unsigned long long a,
                                                    unsigned long long b) {
    unsigned long long d;
    asm("add.rn.f32x2 %0, %1, %2;" : "=l"(d) : "l"(a), "l"(b));
    return d;
}
__device__ __forceinline__ unsigned long long dup2_(float x) {
    unsigned long long d;
    asm("mov.b64 %0, {%1, %1};" : "=l"(d) : "f"(x));
    return d;
}
__device__ __forceinline__ unsigned long long pack2_(float a, float b) {
    unsigned long long d;
    asm("mov.b64 %0, {%1, %2};" : "=l"(d) : "f"(a), "f"(b));
    return d;
}
__device__ __forceinline__ float2 unpack2_(unsigned long long v) {
    float2 r;
    asm("mov.b64 {%0, %1}, %2;" : "=f"(r.x), "=f"(r.y) : "l"(v));
    return r;
}

// ============================================================================
// Phase 1: xproj — R10 kernel body (best measured 615-618 us) with occupancy
// raised 3 -> 4 blocks/SM. Budget check: regs 65536/(4*128)=128 >= 122 used;
// SMEM 4 * 48KB = 192KB <= 227KB. 16 warps/SM.
// Block tile = 64 rows x 128 cols (one gate), 128 threads, 4x16 register tile
// packed f32x2 over cols, XOR-swizzled transposed x tile.
// ============================================================================
#define XS_IDX(i, row) ((i) * 64 + ((row) ^ ((i) & 60)))

__global__ __launch_bounds__(128, 4) void xproj_kernel(
    const float* __restrict__ x,
    const float* __restrict__ Wir, const float* __restrict__ Wiz, const float* __restrict__ Win,
    const float* __restrict__ bir, const float* __restrict__ biz, const float* __restrict__ bin_)
{
    __shared__ __align__(16) float xs[I_SIZE * 64];       // 16384 B
    __shared__ __align__(16) float ws[I_SIZE * H_SIZE];   // 32768 B

    const int g = blockIdx.y;
    const float* __restrict__ W    = (g == 0) ? Wir : (g == 1) ? Wiz : Win;
    const float* __restrict__ bias = (g == 0) ? bir : (g == 1) ? biz : bin_;

    const int tid = threadIdx.x;
    const size_t r_base = (size_t)blockIdx.x * 64;

    const float4* __restrict__ xg4 = (const float4*)(x + r_base * I_SIZE);
    #pragma unroll
    for (int s = 0; s < 8; s++) {
        int idx4 = tid + 128 * s;            // 0..1023 float4s
        float4 v = xg4[idx4];
        int row = idx4 >> 4;
        int i0  = (idx4 & 15) * 4;
        xs[XS_IDX(i0 + 0, row)] = v.x;
        xs[XS_IDX(i0 + 1, row)] = v.y;
        xs[XS_IDX(i0 + 2, row)] = v.z;
        xs[XS_IDX(i0 + 3, row)] = v.w;
    }
    const float4* __restrict__ Wg4 = (const float4*)W;
    #pragma unroll
    for (int s = 0; s < 16; s++) {
        int idx4 = tid + 128 * s;
        ((float4*)ws)[idx4] = Wg4[idx4];
    }
    __syncthreads();

    const int tr = tid & 15;
    const int tc = tid >> 4;
    const int r0 = tr * 4;
    const int c0 = tc * 16;

    unsigned long long accp[4][8];
    #pragma unroll
    for (int r = 0; r < 4; r++)
        #pragma unroll
        for (int c = 0; c < 8; c++)
            accp[r][c] = 0ull;

    #pragma unroll 4
    for (int k = 0; k < I_SIZE; k++) {
        float4 xa = *(const float4*)&xs[XS_IDX(k, r0)];
        const ulonglong2* wr = (const ulonglong2*)&ws[k * H_SIZE + c0];
        ulonglong2 wq0 = wr[0], wq1 = wr[1], wq2 = wr[2], wq3 = wr[3];
        unsigned long long wp[8] = {wq0.x, wq0.y, wq1.x, wq1.y,
                                    wq2.x, wq2.y, wq3.x, wq3.y};
        unsigned long long xd[4] = {dup2_(xa.x), dup2_(xa.y), dup2_(xa.z), dup2_(xa.w)};
        #pragma unroll
        for (int r = 0; r < 4; r++)
            #pragma unroll
            for (int c = 0; c < 8; c++)
                accp[r][c] = fma2_(xd[r], wp[c], accp[r][c]);
    }

    const float4* __restrict__ bp = (const float4*)(bias + c0);
    float4 b0 = bp[0], b1 = bp[1], b2 = bp[2], b3 = bp[3];
    float bv[16] = {b0.x, b0.y, b0.z, b0.w, b1.x, b1.y, b1.z, b1.w,
                    b2.x, b2.y, b2.z, b2.w, b3.x, b3.y, b3.z, b3.w};

    #pragma unroll
    for (int r = 0; r < 4; r++) {
        size_t row = r_base + (size_t)(r0 + r);
        float* op = g_xproj + row * (3 * H_SIZE) + g * H_SIZE + c0;
        #pragma unroll
        for (int q = 0; q < 4; q++) {
            float2 pa = unpack2_(accp[r][2 * q + 0]);
            float2 pb = unpack2_(accp[r][2 * q + 1]);
            float4 o;
            o.x = pa.x + bv[4 * q + 0];
            o.y = pa.y + bv[4 * q + 1];
            o.z = pb.x + bv[4 * q + 2];
            o.w = pb.y + bv[4 * q + 3];
            *(float4*)(op + 4 * q) = o;
        }
    }
}

// ============================================================================
// Phase 2: persistent per-batch GRU recurrence (R13 trimmed version — best
// measured ~2325 us; R14's row-skew regressed and is reverted).
// grid = 128 blocks (2 batch rows each), 384 threads, thread = (gate g, col j).
// Packed FFMA2 dot (8 chains) + add2 reduction; parallel epilogue (g2 row0,
// g1 row1); bhn pre-added; branchless x(t+1) prefetch; classifier deferred.
// ============================================================================
__global__ __launch_bounds__(384, 1) void gru_kernel(
    const float* __restrict__ Whr, const float* __restrict__ Whz, const float* __restrict__ Whn,
    const float* __restrict__ bhn)
{
    __shared__ __align__(16) float h_s[2][H_SIZE];
    __shared__ float r_s[2][H_SIZE];
    __shared__ float z0_s[H_SIZE];                 // z row 0 (gate-1 keeps z1 in reg)
    __shared__ __align__(8) float2 ax1_s[H_SIZE];  // (a1 + bhn, xn1) for row 1

    const int tid = threadIdx.x;
    const int g   = tid >> 7;       // 0=r, 1=z, 2=n
    const int j   = tid & 127;
    const int b0  = blockIdx.x * 2;

    const float* __restrict__ Wh = (g == 0) ? Whr : (g == 1) ? Whz : Whn;

    // Register-resident weight column packed over k pairs (128 regs).
    unsigned long long w2[H_SIZE / 2];
    #pragma unroll
    for (int m = 0; m < H_SIZE / 2; m++)
        w2[m] = pack2_(Wh[(2 * m) * H_SIZE + j], Wh[(2 * m + 1) * H_SIZE + j]);

    const float bhn_j = bhn[j];

    if (tid < 2 * H_SIZE) ((float*)h_s)[tid] = 0.0f;   // h0 = 0
    __syncthreads();

    const float* __restrict__ xp = g_xproj + (size_t)b0 * (3 * H_SIZE) + g * H_SIZE + j;
    const size_t step_stride = (size_t)B_SIZE * 3 * H_SIZE;

    const ulonglong2* __restrict__ h0q = (const ulonglong2*)h_s[0];
    const ulonglong2* __restrict__ h1q = (const ulonglong2*)h_s[1];

    float x0 = xp[0];
    float x1 = xp[3 * H_SIZE];

    for (int t = 0; t < T_STEPS; t++) {
        // branchless prefetch of x(t+1) (t = T-1 re-reads last step, unused)
        int tn = (t + 1 < T_STEPS) ? (t + 1) : t;
        const float* xq = xp + (size_t)tn * step_stride;
        float nx0 = xq[0];
        float nx1 = xq[3 * H_SIZE];

        // acc[row] = sum_k h[row][k] * Wh[k][j] — packed over k, 8 chains.
        unsigned long long p00 = 0ull, p01 = 0ull, p02 = 0ull, p03 = 0ull;
        unsigned long long p10 = 0ull, p11 = 0ull, p12 = 0ull, p13 = 0ull;
        #pragma unroll
        for (int m = 0; m < 16; m++) {
            ulonglong2 va0 = h0q[2 * m];
            ulonglong2 vb0 = h0q[2 * m + 1];
            ulonglong2 va1 = h1q[2 * m];
            ulonglong2 vb1 = h1q[2 * m + 1];
            p00 = fma2_(va0.x, w2[4 * m + 0], p00);
            p01 = fma2_(va0.y, w2[4 * m + 1], p01);
            p02 = fma2_(vb0.x, w2[4 * m + 2], p02);
            p03 = fma2_(vb0.y, w2[4 * m + 3], p03);
            p10 = fma2_(va1.x, w2[4 * m + 0], p10);
            p11 = fma2_(va1.y, w2[4 * m + 1], p11);
            p12 = fma2_(vb1.x, w2[4 * m + 2], p12);
            p13 = fma2_(vb1.y, w2[4 * m + 3], p13);
        }
        // packed reduction: 3 packed adds per row, then one unpack+add
        unsigned long long s0 = add2_(add2_(p00, p01), add2_(p02, p03));
        unsigned long long s1 = add2_(add2_(p10, p11), add2_(p12, p13));
        float2 u0 = unpack2_(s0);
        float2 u1 = unpack2_(s1);
        float acc0 = u0.x + u0.y;
        float acc1 = u1.x + u1.y;

        float z1r = 0.0f;
        if (g == 0) {
            r_s[0][j] = sigmoidf_(x0 + acc0);
            r_s[1][j] = sigmoidf_(x1 + acc1);
        } else if (g == 1) {
            z0_s[j] = sigmoidf_(x0 + acc0);
            z1r     = sigmoidf_(x1 + acc1);
        } else {
            float2 ax;
            ax.x = acc1 + bhn_j;           // pre-add bias
            ax.y = x1;
            ax1_s[j] = ax;
        }
        __syncthreads();   // r, z0, (a1+bhn, xn1) ready

        if (g == 2) {
            // row 0 update (acc0, x0 live in regs)
            float h0o = h_s[0][j];
            float n0  = tanhf_(fmaf(r_s[0][j], acc0 + bhn_j, x0));
            float z0  = z0_s[j];
            float hn0 = fmaf(z0, h0o - n0, n0);   // n + z*(h-n)
            h_s[0][j] = hn0;
            g_hs[((size_t)t * B_SIZE + b0) * H_SIZE + j] = hn0;
        } else if (g == 1) {
            // row 1 update (z1 live in reg)
            float h1o = h_s[1][j];
            float2 ax = ax1_s[j];
            float n1  = tanhf_(fmaf(r_s[1][j], ax.x, ax.y));
            float hn1 = fmaf(z1r, h1o - n1, n1);
            h_s[1][j] = hn1;
            g_hs[((size_t)t * B_SIZE + b0 + 1) * H_SIZE + j] = hn1;
        }
        __syncthreads();   // h_new ready for next step's dot

        x0 = nx0;
        x1 = nx1;
    }
}

// ============================================================================
// Phase 3: classifier out[o] = sigmoid(dot(hs[o,:], Wc) + bc).
// Warp per output; memory-bound (268 MB streamed).
// ============================================================================
__global__ __launch_bounds__(256) void cls_kernel(
    const float* __restrict__ Wc, const float* __restrict__ bc,
    float* __restrict__ out)
{
    const int lane = threadIdx.x & 31;
    const size_t o = (size_t)blockIdx.x * 8 + (threadIdx.x >> 5);

    float4 h4 = *(const float4*)&g_hs[o * H_SIZE + lane * 4];
    float4 w4 = *(const float4*)&Wc[lane * 4];
    float v = fmaf(h4.x, w4.x, fmaf(h4.y, w4.y, fmaf(h4.z, w4.z, h4.w * w4.w)));
    #pragma unroll
    for (int off = 16; off > 0; off >>= 1)
        v += __shfl_down_sync(0xffffffffu, v, off);
    if (lane == 0) out[o] = sigmoidf_(v + bc[0]);
}

// ============================================================================
extern "C" void kernel_launch(void* const* d_in, const int* in_sizes, int n_in,
                              void* d_out, int out_size)
{
    const float* x    = (const float*)d_in[0];
    const float* Wir  = (const float*)d_in[1];
    const float* Wiz  = (const float*)d_in[2];
    const float* Win  = (const float*)d_in[3];
    const float* bir  = (const float*)d_in[4];
    const float* biz  = (const float*)d_in[5];
    const float* bin_ = (const float*)d_in[6];
    const float* Whr  = (const float*)d_in[7];
    const float* Whz  = (const float*)d_in[8];
    const float* Whn  = (const float*)d_in[9];
    const float* bhn  = (const float*)d_in[10];
    const float* Wc   = (const float*)d_in[11];
    const float* bc   = (const float*)d_in[12];
    float* out = (float*)d_out;

    // Phase 1: input projections (R10 body, 4 blocks/SM).
    dim3 grid1((T_STEPS * B_SIZE) / 64, 3);
    xproj_kernel<<<grid1, 128>>>(x, Wir, Wiz, Win, bir, biz, bin_);

    // Phase 2: sequential recurrence, batch-parallel across 128 blocks.
    gru_kernel<<<B_SIZE / 2, 384>>>(Whr, Whz, Whn, bhn);

    // Phase 3: classifier over all T*B hidden states.
    cls_kernel<<<(T_STEPS * B_SIZE) / 8, 256>>>(Wc, bc, out);
}

// round 17
// speedup vs baseline: 1.1907x; 1.1114x over previous
#include <cuda_runtime.h>
#include <cuda_bf16.h>
#include <cstdint>
#include <cstddef>

#define T_STEPS 2048
#define B_SIZE  256
#define I_SIZE  64
#define H_SIZE  128

// Scratch: input projections x@Wi + bi, layout [T][B][3*H] (805 MB)
__device__ float g_xproj[(size_t)T_STEPS * B_SIZE * 3 * H_SIZE];
// Scratch: hidden states hs [T][B][H] (268 MB) for deferred classifier
__device__ float g_hs[(size_t)T_STEPS * B_SIZE * H_SIZE];
// Pre-converted W (bf16 hi/lo), layout [n_global=g*128+j][k], n=384, k=64
__device__ __align__(16) __nv_bfloat16 g_wbh[384 * 64];
__device__ __align__(16) __nv_bfloat16 g_wbl[384 * 64];

__device__ __forceinline__ float sigmoidf_(float x) {
    return 1.0f / (1.0f + __expf(-x));
}
__device__ __forceinline__ float tanhf_(float x) {
    return 1.0f - 2.0f / (1.0f + __expf(2.0f * x));
}

// ---- packed f32x2 helpers (Blackwell FFMA2 / FADD2) ------------------------
__device__ __forceinline__ unsigned long long fma2_(unsigned long long a,
                                                    unsigned long long b,
                                                    unsigned long long c) {
    unsigned long long d;
    asm("fma.rn.f32x2 %0, %1, %2, %3;" : "=l"(d) : "l"(a), "l"(b), "l"(c));
    return d;
}
__device__ __forceinline__ unsigned long long add2_(unsigned long long a,
                                                    unsigned long long b) {
    unsigned long long d;
    asm("add.rn.f32x2 %0, %1, %2;" : "=l"(d) : "l"(a), "l"(b));
    return d;
}
__device__ __forceinline__ unsigned long long pack2_(float a, float b) {
    unsigned long long d;
    asm("mov.b64 %0, {%1, %2};" : "=l"(d) : "f"(a), "f"(b));
    return d;
}
__device__ __forceinline__ float2 unpack2_(unsigned long long v) {
    float2 r;
    asm("mov.b64 {%0, %1}, %2;" : "=f"(r.x), "=f"(r.y) : "l"(v));
    return r;
}

// ---- HMMA m16n8k16 bf16 (arch-portable mma.sync, works on compute_103) -----
__device__ __forceinline__ void mma16816_(float& d0, float& d1, float& d2, float& d3,
                                          uint32_t a0, uint32_t a1, uint32_t a2, uint32_t a3,
                                          uint32_t b0, uint32_t b1) {
    asm volatile(
        "mma.sync.aligned.m16n8k16.row.col.f32.bf16.bf16.f32 "
        "{%0,%1,%2,%3}, {%4,%5,%6,%7}, {%8,%9}, {%0,%1,%2,%3};"
        : "+f"(d0), "+f"(d1), "+f"(d2), "+f"(d3)
        : "r"(a0), "r"(a1), "r"(a2), "r"(a3), "r"(b0), "r"(b1));
}

// ============================================================================
// Kernel 0: convert W (fp32 [k][n] per gate) -> bf16 hi/lo [n_global][k].
// Tiny (24576 elems); runs once per launch.
// ============================================================================
__global__ __launch_bounds__(256) void wconv_kernel(
    const float* __restrict__ Wir, const float* __restrict__ Wiz, const float* __restrict__ Win)
{
    int idx = blockIdx.x * 256 + threadIdx.x;   // 0..24575 = n_global*64 + k
    int k  = idx & 63;
    int ng = idx >> 6;          // 0..383
    int g  = ng >> 7;
    int nn = ng & 127;
    const float* Wg = (g == 0) ? Wir : (g == 1) ? Wiz : Win;
    float v = Wg[k * H_SIZE + nn];
    __nv_bfloat16 h = __float2bfloat16(v);
    __nv_bfloat16 l = __float2bfloat16(v - __bfloat162float(h));
    g_wbh[idx] = h;
    g_wbl[idx] = l;
}

// ============================================================================
// Phase 1 (tensor cores via mma.sync): one block per 128-row tile (grid 4096),
// 256 threads = 8 warps; warp w owns rows [w*16, w*16+16).
// SMEM rows padded to 72 bf16 (144 B) -> conflict-free fragment loads.
// 3-term bf16 hi/lo split, fp32 accumulate in registers, direct STG out.
// ============================================================================
#define XSTRB 144            // padded row stride in bytes (72 bf16)
#define SM_BIAS 0            // 384 floats = 1536 B
#define SM_XHI  1536         // 128*144 = 18432
#define SM_XLO  (SM_XHI + 18432)
#define SM_WHI  (SM_XLO + 18432)   // 384*144 = 55296
#define SM_WLO  (SM_WHI + 55296)
#define SM_TOTAL (SM_WLO + 55296)  // 148992 B

__global__ __launch_bounds__(256) void xproj_mma_kernel(
    const float* __restrict__ x,
    const float* __restrict__ bir, const float* __restrict__ biz, const float* __restrict__ bin_)
{
    extern __shared__ char sm[];
    float* bias_s = (float*)(sm + SM_BIAS);

    const int tid  = threadIdx.x;
    const int wid  = tid >> 5;
    const int lane = tid & 31;
    const size_t r_base = (size_t)blockIdx.x * 128;

    // bias
    for (int c = tid; c < 384; c += 256) {
        const float* bp = (c < 128) ? bir : (c < 256) ? biz : bin_;
        bias_s[c] = bp[c & 127];
    }

    // W tiles: copy pre-converted bf16 (uint4 = 8 bf16) into padded SMEM.
    {
        const uint4* __restrict__ sh = (const uint4*)g_wbh;   // 3072 uint4
        const uint4* __restrict__ sl = (const uint4*)g_wbl;
        #pragma unroll
        for (int s = 0; s < 12; s++) {
            int i4 = tid + 256 * s;         // 0..3071
            int n  = i4 >> 3;
            int kb = i4 & 7;
            uint4 vh = sh[i4];
            uint4 vl = sl[i4];
            *(uint4*)(sm + SM_WHI + n * XSTRB + kb * 16) = vh;
            *(uint4*)(sm + SM_WLO + n * XSTRB + kb * 16) = vl;
        }
    }
    // x tile: 2048 float4, convert to bf16 hi/lo into padded SMEM.
    {
        const float4* __restrict__ xg4 = (const float4*)(x + r_base * I_SIZE);
        #pragma unroll
        for (int s = 0; s < 8; s++) {
            int i4  = tid + 256 * s;        // 0..2047
            int row = i4 >> 4;              // 16 float4 per row
            int kb  = i4 & 15;              // covers k = kb*4 .. +3
            float4 v = xg4[i4];
            __nv_bfloat162 ph0 = __floats2bfloat162_rn(v.x, v.y);
            __nv_bfloat162 ph1 = __floats2bfloat162_rn(v.z, v.w);
            float lx = v.x - __bfloat162float(ph0.x);
            float ly = v.y - __bfloat162float(ph0.y);
            float lz = v.z - __bfloat162float(ph1.x);
            float lw = v.w - __bfloat162float(ph1.y);
            __nv_bfloat162 pl0 = __floats2bfloat162_rn(lx, ly);
            __nv_bfloat162 pl1 = __floats2bfloat162_rn(lz, lw);
            char* hb = sm + SM_XHI + row * XSTRB + kb * 8;
            char* lb = sm + SM_XLO + row * XSTRB + kb * 8;
            *(__nv_bfloat162*)(hb)     = ph0;
            *(__nv_bfloat162*)(hb + 4) = ph1;
            *(__nv_bfloat162*)(lb)     = pl0;
            *(__nv_bfloat162*)(lb + 4) = pl1;
        }
    }
    __syncthreads();

    // A fragments for this warp's 16 rows: [kstep][4 regs], hi and lo.
    uint32_t ah[4][4], al[4][4];
    {
        int r0 = wid * 16 + (lane >> 2);
        int kp = (lane & 3) * 2;
        #pragma unroll
        for (int kk = 0; kk < 4; kk++) {
            uint32_t o = r0 * XSTRB + (kk * 16 + kp) * 2;
            ah[kk][0] = *(const uint32_t*)(sm + SM_XHI + o);
            ah[kk][1] = *(const uint32_t*)(sm + SM_XHI + o + 8 * XSTRB);
            ah[kk][2] = *(const uint32_t*)(sm + SM_XHI + o + 16);
            ah[kk][3] = *(const uint32_t*)(sm + SM_XHI + o + 8 * XSTRB + 16);
            al[kk][0] = *(const uint32_t*)(sm + SM_XLO + o);
            al[kk][1] = *(const uint32_t*)(sm + SM_XLO + o + 8 * XSTRB);
            al[kk][2] = *(const uint32_t*)(sm + SM_XLO + o + 16);
            al[kk][3] = *(const uint32_t*)(sm + SM_XLO + o + 8 * XSTRB + 16);
        }
    }

    // 48 n-tiles of 8 cols; D in registers; 12 HMMA per tile.
    const int nrow_off = (lane >> 2);
    const int kp = (lane & 3) * 2;
    #pragma unroll 2
    for (int ct = 0; ct < 48; ct++) {
        int n0 = ct * 8;
        float d0 = 0.f, d1 = 0.f, d2 = 0.f, d3 = 0.f;
        uint32_t obase = (uint32_t)(n0 + nrow_off) * XSTRB + kp * 2;
        #pragma unroll
        for (int kk = 0; kk < 4; kk++) {
            uint32_t ob = obase + kk * 32;
            uint32_t bh0 = *(const uint32_t*)(sm + SM_WHI + ob);
            uint32_t bh1 = *(const uint32_t*)(sm + SM_WHI + ob + 16);
            uint32_t bl0 = *(const uint32_t*)(sm + SM_WLO + ob);
            uint32_t bl1 = *(const uint32_t*)(sm + SM_WLO + ob + 16);
            mma16816_(d0, d1, d2, d3, ah[kk][0], ah[kk][1], ah[kk][2], ah[kk][3], bh0, bh1);
            mma16816_(d0, d1, d2, d3, ah[kk][0], ah[kk][1], ah[kk][2], ah[kk][3], bl0, bl1);
            mma16816_(d0, d1, d2, d3, al[kk][0], al[kk][1], al[kk][2], al[kk][3], bh0, bh1);
        }
        int col = n0 + (lane & 3) * 2;
        size_t row0 = r_base + wid * 16 + (lane >> 2);
        float b0 = bias_s[col], b1 = bias_s[col + 1];
        float2 o0; o0.x = d0 + b0; o0.y = d1 + b1;
        float2 o1; o1.x = d2 + b0; o1.y = d3 + b1;
        *(float2*)(g_xproj + row0 * 384 + col)       = o0;
        *(float2*)(g_xproj + (row0 + 8) * 384 + col) = o1;
    }
}

// ============================================================================
// Phase 2: persistent per-batch GRU recurrence (best measured config, R13/R15).
// ============================================================================
__global__ __launch_bounds__(384, 1) void gru_kernel(
    const float* __restrict__ Whr, const float* __restrict__ Whz, const float* __restrict__ Whn,
    const float* __restrict__ bhn)
{
    __shared__ __align__(16) float h_s[2][H_SIZE];
    __shared__ float r_s[2][H_SIZE];
    __shared__ float z0_s[H_SIZE];
    __shared__ __align__(8) float2 ax1_s[H_SIZE];

    const int tid = threadIdx.x;
    const int g   = tid >> 7;
    const int j   = tid & 127;
    const int b0  = blockIdx.x * 2;

    const float* __restrict__ Wh = (g == 0) ? Whr : (g == 1) ? Whz : Whn;

    unsigned long long w2[H_SIZE / 2];
    #pragma unroll
    for (int m = 0; m < H_SIZE / 2; m++)
        w2[m] = pack2_(Wh[(2 * m) * H_SIZE + j], Wh[(2 * m + 1) * H_SIZE + j]);

    const float bhn_j = bhn[j];

    if (tid < 2 * H_SIZE) ((float*)h_s)[tid] = 0.0f;
    __syncthreads();

    const float* __restrict__ xp = g_xproj + (size_t)b0 * (3 * H_SIZE) + g * H_SIZE + j;
    const size_t step_stride = (size_t)B_SIZE * 3 * H_SIZE;

    const ulonglong2* __restrict__ h0q = (const ulonglong2*)h_s[0];
    const ulonglong2* __restrict__ h1q = (const ulonglong2*)h_s[1];

    float x0 = xp[0];
    float x1 = xp[3 * H_SIZE];

    for (int t = 0; t < T_STEPS; t++) {
        int tn = (t + 1 < T_STEPS) ? (t + 1) : t;
        const float* xq = xp + (size_t)tn * step_stride;
        float nx0 = xq[0];
        float nx1 = xq[3 * H_SIZE];

        unsigned long long p00 = 0ull, p01 = 0ull, p02 = 0ull, p03 = 0ull;
        unsigned long long p10 = 0ull, p11 = 0ull, p12 = 0ull, p13 = 0ull;
        #pragma unroll
        for (int m = 0; m < 16; m++) {
            ulonglong2 va0 = h0q[2 * m];
            ulonglong2 vb0 = h0q[2 * m + 1];
            ulonglong2 va1 = h1q[2 * m];
            ulonglong2 vb1 = h1q[2 * m + 1];
            p00 = fma2_(va0.x, w2[4 * m + 0], p00);
            p01 = fma2_(va0.y, w2[4 * m + 1], p01);
            p02 = fma2_(vb0.x, w2[4 * m + 2], p02);
            p03 = fma2_(vb0.y, w2[4 * m + 3], p03);
            p10 = fma2_(va1.x, w2[4 * m + 0], p10);
            p11 = fma2_(va1.y, w2[4 * m + 1], p11);
            p12 = fma2_(vb1.x, w2[4 * m + 2], p12);
            p13 = fma2_(vb1.y, w2[4 * m + 3], p13);
        }
        unsigned long long s0 = add2_(add2_(p00, p01), add2_(p02, p03));
        unsigned long long s1 = add2_(add2_(p10, p11), add2_(p12, p13));
        float2 u0 = unpack2_(s0);
        float2 u1 = unpack2_(s1);
        float acc0 = u0.x + u0.y;
        float acc1 = u1.x + u1.y;

        float z1r = 0.0f;
        if (g == 0) {
            r_s[0][j] = sigmoidf_(x0 + acc0);
            r_s[1][j] = sigmoidf_(x1 + acc1);
        } else if (g == 1) {
            z0_s[j] = sigmoidf_(x0 + acc0);
            z1r     = sigmoidf_(x1 + acc1);
        } else {
            float2 ax;
            ax.x = acc1 + bhn_j;
            ax.y = x1;
            ax1_s[j] = ax;
        }
        __syncthreads();

        if (g == 2) {
            float h0o = h_s[0][j];
            float n0  = tanhf_(fmaf(r_s[0][j], acc0 + bhn_j, x0));
            float z0  = z0_s[j];
            float hn0 = fmaf(z0, h0o - n0, n0);
            h_s[0][j] = hn0;
            g_hs[((size_t)t * B_SIZE + b0) * H_SIZE + j] = hn0;
        } else if (g == 1) {
            float h1o = h_s[1][j];
            float2 ax = ax1_s[j];
            float n1  = tanhf_(fmaf(r_s[1][j], ax.x, ax.y));
            float hn1 = fmaf(z1r, h1o - n1, n1);
            h_s[1][j] = hn1;
            g_hs[((size_t)t * B_SIZE + b0 + 1) * H_SIZE + j] = hn1;
        }
        __syncthreads();

        x0 = nx0;
        x1 = nx1;
    }
}

// ============================================================================
// Phase 3: classifier out[o] = sigmoid(dot(hs[o,:], Wc) + bc).
// ============================================================================
__global__ __launch_bounds__(256) void cls_kernel(
    const float* __restrict__ Wc, const float* __restrict__ bc,
    float* __restrict__ out)
{
    const int lane = threadIdx.x & 31;
    const size_t o = (size_t)blockIdx.x * 8 + (threadIdx.x >> 5);

    float4 h4 = *(const float4*)&g_hs[o * H_SIZE + lane * 4];
    float4 w4 = *(const float4*)&Wc[lane * 4];
    float v = fmaf(h4.x, w4.x, fmaf(h4.y, w4.y, fmaf(h4.z, w4.z, h4.w * w4.w)));
    #pragma unroll
    for (int off = 16; off > 0; off >>= 1)
        v += __shfl_down_sync(0xffffffffu, v, off);
    if (lane == 0) out[o] = sigmoidf_(v + bc[0]);
}

// ============================================================================
extern "C" void kernel_launch(void* const* d_in, const int* in_sizes, int n_in,
                              void* d_out, int out_size)
{
    const float* x    = (const float*)d_in[0];
    const float* Wir  = (const float*)d_in[1];
    const float* Wiz  = (const float*)d_in[2];
    const float* Win  = (const float*)d_in[3];
    const float* bir  = (const float*)d_in[4];
    const float* biz  = (const float*)d_in[5];
    const float* bin_ = (const float*)d_in[6];
    const float* Whr  = (const float*)d_in[7];
    const float* Whz  = (const float*)d_in[8];
    const float* Whn  = (const float*)d_in[9];
    const float* bhn  = (const float*)d_in[10];
    const float* Wc   = (const float*)d_in[11];
    const float* bc   = (const float*)d_in[12];
    float* out = (float*)d_out;

    // Kernel 0: W -> bf16 hi/lo (once).
    wconv_kernel<<<96, 256>>>(Wir, Wiz, Win);

    // Phase 1: tensor-core input projections (mma.sync bf16 hi/lo, fp32 acc).
    static int smem_set = 0;
    if (!smem_set) {
        cudaFuncSetAttribute(xproj_mma_kernel,
                             cudaFuncAttributeMaxDynamicSharedMemorySize, SM_TOTAL);
        smem_set = 1;
    }
    xproj_mma_kernel<<<(T_STEPS * B_SIZE) / 128, 256, SM_TOTAL>>>(x, bir, biz, bin_);

    // Phase 2: sequential recurrence, batch-parallel across 128 blocks.
    gru_kernel<<<B_SIZE / 2, 384>>>(Whr, Whz, Whn, bhn);

    // Phase 3: classifier over all T*B hidden states.
    cls_kernel<<<(T_STEPS * B_SIZE) / 8, 256>>>(Wc, bc, out);
}